// round 17
// baseline (speedup 1.0000x reference)
#include <cuda_runtime.h>
#include <cuda_fp16.h>
#include <cstdint>

#define NQ      4096
#define NDB     65536
#define DIM     32
#define DAUX    32
#define KNN     5
#define NSLAB   (NDB / 32)         // 2048 32-point slabs
#define NSPLIT  4                  // db quarters per query tile
#define QPC     64                 // queries per CTA (4 m-tiles)
#define NS      (NSLAB / NSPLIT / 2)  // 256 slabs per warp (eighth of db)
#define NLIST   (NSPLIT * 2)       // 8 candidate lists per query
#define BIGF    3.0e38f

// ---------------- global scratch ----------------
// g_Bf: fp16 hi frag-packed db. Per 32-pt slab s: 128 uint4 =
//   [ntile j=0..3][lane 0..31]; lane uint4 = {ks0.b0, ks0.b1, ks1.b0, ks1.b1}
//   for point p = s*32 + j*8 + (lane>>2), k per m16n8k16 B layout.
__device__ uint4 g_Bf[NSLAB * 128];           // 4 MB
__device__ float g_hs[NDB];                   // 0.5*||db||^2
__device__ int   g_ci[NQ * NLIST * KNN];      // candidate indices

// ---------------- helpers ----------------
__device__ __forceinline__ uint32_t h2u(__half a, __half b) {
    __half2 h = __halves2half2(a, b);
    return *(uint32_t*)&h;
}
__device__ __forceinline__ void mma16(float* c, const uint32_t* a,
                                      uint32_t b0, uint32_t b1) {
    asm("mma.sync.aligned.m16n8k16.row.col.f32.f16.f16.f32 "
        "{%0,%1,%2,%3}, {%4,%5,%6,%7}, {%8,%9}, {%0,%1,%2,%3};"
        : "+f"(c[0]), "+f"(c[1]), "+f"(c[2]), "+f"(c[3])
        : "r"(a[0]), "r"(a[1]), "r"(a[2]), "r"(a[3]), "r"(b0), "r"(b1));
}
__device__ __forceinline__ void topk_ins(float* ts, int* ti, float s, int pi) {
    if (s < ts[4]) {
        ts[4] = s; ti[4] = pi;
        if (ts[4] < ts[3]) { float f = ts[3]; ts[3] = ts[4]; ts[4] = f; int i = ti[3]; ti[3] = ti[4]; ti[4] = i; }
        if (ts[3] < ts[2]) { float f = ts[2]; ts[2] = ts[3]; ts[3] = f; int i = ti[2]; ti[2] = ti[3]; ti[3] = i; }
        if (ts[2] < ts[1]) { float f = ts[1]; ts[1] = ts[2]; ts[2] = f; int i = ti[1]; ti[1] = ti[2]; ti[2] = i; }
        if (ts[1] < ts[0]) { float f = ts[0]; ts[0] = ts[1]; ts[1] = f; int i = ti[0]; ti[0] = ti[1]; ti[1] = i; }
    }
}

// ---------------------------------------------------------------------------
// prep_hs: 0.5*||db||^2 per point.
// ---------------------------------------------------------------------------
__global__ void prep_hs(const float* __restrict__ db) {
    const unsigned FULL = 0xffffffffu;
    const int p = blockIdx.x * 32 + (threadIdx.x >> 3);
    const int j = threadIdx.x & 7;
    float4 v = *(const float4*)(db + p * DIM + j * 4);
    float s = v.x * v.x + v.y * v.y + v.z * v.z + v.w * v.w;
    s += __shfl_xor_sync(FULL, s, 4, 8);
    s += __shfl_xor_sync(FULL, s, 2, 8);
    s += __shfl_xor_sync(FULL, s, 1, 8);
    if (j == 0) g_hs[p] = 0.5f * s;
}

// ---------------------------------------------------------------------------
// prep_bf: fp16 hi frag-packed db. One thread per (slab, ntile, lane).
// ---------------------------------------------------------------------------
__global__ void prep_bf(const float* __restrict__ db) {
    const int gid  = blockIdx.x * 256 + threadIdx.x;   // 0 .. NSLAB*128-1
    const int s    = gid >> 7;
    const int r    = gid & 127;
    const int j    = r >> 5;
    const int lane = r & 31;
    const int tig  = lane & 3;
    const int p    = s * 32 + j * 8 + (lane >> 2);

    const float* src = db + p * DIM;
    __half hi[8];
#pragma unroll
    for (int e = 0; e < 8; ++e) {
        // k-order: {2t,2t+1, 2t+8,2t+9, 2t+16,2t+17, 2t+24,2t+25}
        int k = 2 * tig + (e & 1) + 8 * (e >> 1);
        hi[e] = __float2half_rn(src[k]);
    }
    uint4 uh;
    uh.x = h2u(hi[0], hi[1]); uh.y = h2u(hi[2], hi[3]);
    uh.z = h2u(hi[4], hi[5]); uh.w = h2u(hi[6], hi[7]);
    g_Bf[s * 128 + j * 32 + lane] = uh;
}

// ---------------------------------------------------------------------------
// main: 256 CTAs (64 q-tiles x 4 db-splits), 256 threads, 2 CTAs/SM.
// hi-only fp16 scoring, 32-pt slabs, DEPTH-2 B prefetch (covers L2 latency).
// ---------------------------------------------------------------------------
__global__ void __launch_bounds__(256, 2)
knn_mma(const float* __restrict__ q) {
    const unsigned FULL = 0xffffffffu;
    const int tid  = threadIdx.x;
    const int lane = tid & 31;
    const int tig  = lane & 3;
    const int wid  = tid >> 5;
    const int mi   = wid & 3;              // m-tile within CTA (16 queries)
    const int ph   = wid >> 2;             // p-half within this CTA's db split
    const int qb   = blockIdx.x >> 2;      // 0..63 query tile
    const int sp   = blockIdx.x & 3;       // db split (quarter)
    const int w8   = sp * 2 + ph;          // candidate-list slot 0..7

    const int r0 = qb * QPC + mi * 16 + (lane >> 2);  // this thread's 2 queries
    const int r1 = r0 + 8;

    // ---- A fragments (hi only): Ahi[ks][a0..a3] ----
    uint32_t Ahi[2][4];
    {
        const float* q0 = q + r0 * DIM;
        const float* q1 = q + r1 * DIM;
#pragma unroll
        for (int ks = 0; ks < 2; ++ks) {
            int kb = 16 * ks + 2 * tig;
            Ahi[ks][0] = h2u(__float2half_rn(q0[kb]),     __float2half_rn(q0[kb + 1]));
            Ahi[ks][1] = h2u(__float2half_rn(q1[kb]),     __float2half_rn(q1[kb + 1]));
            Ahi[ks][2] = h2u(__float2half_rn(q0[kb + 8]), __float2half_rn(q0[kb + 9]));
            Ahi[ks][3] = h2u(__float2half_rn(q1[kb + 8]), __float2half_rn(q1[kb + 9]));
        }
    }

    float tsA[KNN], tsB[KNN];
    int   tiA[KNN], tiB[KNN];
#pragma unroll
    for (int k = 0; k < KNN; ++k) {
        tsA[k] = BIGF; tiA[k] = 0;
        tsB[k] = BIGF; tiB[k] = 0;
    }

    // ---- stream 32-point slabs with DEPTH-2 prefetch ----
    const int sg0 = sp * (NSLAB / NSPLIT) + ph * NS;   // first slab
    const uint4* bb = g_Bf + (size_t)sg0 * 128 + lane;
    const float* hp = g_hs + sg0 * 32 + 2 * tig;

    uint4 nb0  = bb[0],       nb1  = bb[32];
    uint4 nb2  = bb[64],      nb3  = bb[96];
    uint4 nnb0 = bb[128],     nnb1 = bb[160];
    uint4 nnb2 = bb[192],     nnb3 = bb[224];

    for (int t = 0; t < NS; ++t) {
        uint4 b0 = nb0, b1 = nb1, b2 = nb2, b3 = nb3;
        nb0 = nnb0; nb1 = nnb1; nb2 = nnb2; nb3 = nnb3;
        if (t + 2 < NS) {
            const uint4* bn = bb + (size_t)(t + 2) * 128;
            nnb0 = bn[0];  nnb1 = bn[32];
            nnb2 = bn[64]; nnb3 = bn[96];
        }

        // four independent chains, depth 2 (one per n-tile)
        float c0[4] = {0.f, 0.f, 0.f, 0.f};
        float c1[4] = {0.f, 0.f, 0.f, 0.f};
        float c2[4] = {0.f, 0.f, 0.f, 0.f};
        float c3[4] = {0.f, 0.f, 0.f, 0.f};
        mma16(c0, Ahi[0], b0.x, b0.y);
        mma16(c1, Ahi[0], b1.x, b1.y);
        mma16(c2, Ahi[0], b2.x, b2.y);
        mma16(c3, Ahi[0], b3.x, b3.y);
        mma16(c0, Ahi[1], b0.z, b0.w);
        mma16(c1, Ahi[1], b1.z, b1.w);
        mma16(c2, Ahi[1], b2.z, b2.w);
        mma16(c3, Ahi[1], b3.z, b3.w);

        const float* hb = hp + (size_t)t * 32;
        float2 h0 = *(const float2*)hb;
        float2 h1 = *(const float2*)(hb + 8);
        float2 h2 = *(const float2*)(hb + 16);
        float2 h3 = *(const float2*)(hb + 24);

        // approx scores (selection only)
        float sA0 = h0.x - c0[0], sA1 = h0.y - c0[1];
        float sA2 = h1.x - c1[0], sA3 = h1.y - c1[1];
        float sA4 = h2.x - c2[0], sA5 = h2.y - c2[1];
        float sA6 = h3.x - c3[0], sA7 = h3.y - c3[1];
        float sB0 = h0.x - c0[2], sB1 = h0.y - c0[3];
        float sB2 = h1.x - c1[2], sB3 = h1.y - c1[3];
        float sB4 = h2.x - c2[2], sB5 = h2.y - c2[3];
        float sB6 = h3.x - c3[2], sB7 = h3.y - c3[3];

        const int p0 = (sg0 + t) * 32 + 2 * tig;

        // min-tree early-out per list
        float mA = fminf(fminf(fminf(sA0, sA1), fminf(sA2, sA3)),
                         fminf(fminf(sA4, sA5), fminf(sA6, sA7)));
        if (mA < tsA[4]) {
            topk_ins(tsA, tiA, sA0, p0);      topk_ins(tsA, tiA, sA1, p0 + 1);
            topk_ins(tsA, tiA, sA2, p0 + 8);  topk_ins(tsA, tiA, sA3, p0 + 9);
            topk_ins(tsA, tiA, sA4, p0 + 16); topk_ins(tsA, tiA, sA5, p0 + 17);
            topk_ins(tsA, tiA, sA6, p0 + 24); topk_ins(tsA, tiA, sA7, p0 + 25);
        }
        float mB = fminf(fminf(fminf(sB0, sB1), fminf(sB2, sB3)),
                         fminf(fminf(sB4, sB5), fminf(sB6, sB7)));
        if (mB < tsB[4]) {
            topk_ins(tsB, tiB, sB0, p0);      topk_ins(tsB, tiB, sB1, p0 + 1);
            topk_ins(tsB, tiB, sB2, p0 + 8);  topk_ins(tsB, tiB, sB3, p0 + 9);
            topk_ins(tsB, tiB, sB4, p0 + 16); topk_ins(tsB, tiB, sB5, p0 + 17);
            topk_ins(tsB, tiB, sB6, p0 + 24); topk_ins(tsB, tiB, sB7, p0 + 25);
        }

        if ((t & 15) == 15) __syncthreads();    // keep warps in L1 window
    }

    // ---- quad-merge (4 lanes share each query); write 5 indices per list ----
#pragma unroll
    for (int l = 0; l < 2; ++l) {
        float c0_ = l ? tsB[0] : tsA[0], c1_ = l ? tsB[1] : tsA[1],
              c2_ = l ? tsB[2] : tsA[2], c3_ = l ? tsB[3] : tsA[3],
              c4_ = l ? tsB[4] : tsA[4];
        int   j0 = l ? tiB[0] : tiA[0], j1 = l ? tiB[1] : tiA[1],
              j2 = l ? tiB[2] : tiA[2], j3 = l ? tiB[3] : tiA[3],
              j4 = l ? tiB[4] : tiA[4];
        const int qi = l ? r1 : r0;

#pragma unroll
        for (int k = 0; k < KNN; ++k) {
            float m  = c0_;
            int   ml = lane;
            float om = __shfl_xor_sync(FULL, m, 1, 4);
            int   ol = __shfl_xor_sync(FULL, ml, 1, 4);
            if (om < m || (om == m && ol < ml)) { m = om; ml = ol; }
            om = __shfl_xor_sync(FULL, m, 2, 4);
            ol = __shfl_xor_sync(FULL, ml, 2, 4);
            if (om < m || (om == m && ol < ml)) { m = om; ml = ol; }
            int wi = __shfl_sync(FULL, j0, ml & 3, 4);
            if (lane == ml) {
                c0_ = c1_; c1_ = c2_; c2_ = c3_; c3_ = c4_; c4_ = BIGF;
                j0 = j1; j1 = j2; j2 = j3; j3 = j4;
            }
            if (tig == 0)
                g_ci[(qi * NLIST + w8) * KNN + k] = wi;
        }
    }
}

// ---------------------------------------------------------------------------
// merge: one warp per query; 40 candidate indices -> EXACT fp32 distances
// -> top-5 -> weighted aux gather
// ---------------------------------------------------------------------------
__device__ __forceinline__ float dist2(const float* __restrict__ q,
                                       const float* __restrict__ db,
                                       int gw, int pi) {
    float s = 0.f;
#pragma unroll
    for (int d = 0; d < 8; ++d) {
        float4 a = *(const float4*)(q + gw * DIM + d * 4);
        float4 b = *(const float4*)(db + pi * DIM + d * 4);
        float dx = a.x - b.x, dy = a.y - b.y, dz = a.z - b.z, dw = a.w - b.w;
        s += dx * dx + dy * dy + dz * dz + dw * dw;
    }
    return s;
}

__global__ void merge_kernel(const float* __restrict__ q,
                             const float* __restrict__ db,
                             const float* __restrict__ aux,
                             float* __restrict__ out) {
    const unsigned FULL = 0xffffffffu;
    const int gw   = (blockIdx.x * blockDim.x + threadIdx.x) >> 5;
    const int lane = threadIdx.x & 31;
    if (gw >= NQ) return;

    const int NC = NLIST * KNN;                 // 40
    int   ilo = g_ci[gw * NC + lane];
    int   ihi = (lane < NC - 32) ? g_ci[gw * NC + 32 + lane] : 0;

    // exact squared distances (disjoint db ranges -> no duplicate indices)
    float clo = dist2(q, db, gw, ilo);
    float chi = (lane < NC - 32) ? dist2(q, db, gw, ihi) : BIGF;
    if (chi < clo) { float f = clo; clo = chi; chi = f; int i = ilo; ilo = ihi; ihi = i; }

    float wk[KNN]; int bk[KNN];
    float wsum = 0.f;
#pragma unroll
    for (int k = 0; k < KNN; ++k) {
        float m  = clo;
        int   ml = lane;
#pragma unroll
        for (int off = 16; off; off >>= 1) {
            float om = __shfl_xor_sync(FULL, m, off);
            int   ol = __shfl_xor_sync(FULL, ml, off);
            if (om < m || (om == m && ol < ml)) { m = om; ml = ol; }
        }
        int wi = __shfl_sync(FULL, ilo, ml);
        float dist = sqrtf(fmaxf(m, 0.0f));
        float wgt  = 1.0f / (dist + 1e-6f);
        wk[k] = wgt; bk[k] = wi; wsum += wgt;
        if (lane == ml) { clo = chi; ilo = ihi; chi = BIGF; }
    }

    float acc = 0.f;
#pragma unroll
    for (int k = 0; k < KNN; ++k)
        acc += wk[k] * aux[bk[k] * DAUX + lane];
    out[gw * DAUX + lane] = acc / wsum;
}

// ---------------------------------------------------------------------------
extern "C" void kernel_launch(void* const* d_in, const int* in_sizes, int n_in,
                              void* d_out, int out_size) {
    const float* q   = (const float*)d_in[0];   // embedding_features [4096,32]
    const float* db  = (const float*)d_in[1];   // db_embedding      [65536,32]
    const float* aux = (const float*)d_in[2];   // auxiliary_features[65536,32]
    float* out = (float*)d_out;                 // [4096,32]

    prep_hs<<<NDB / 32, 256>>>(db);
    prep_bf<<<NSLAB * 128 / 256, 256>>>(db);
    knn_mma<<<(NQ / QPC) * NSPLIT, 256>>>(q);
    merge_kernel<<<NQ / 8, 256>>>(q, db, aux, out);
}